// round 6
// baseline (speedup 1.0000x reference)
#include <cuda_runtime.h>
#include <cuda_bf16.h>
#include <cstdint>

#define NNODES 20000
#define NPAD   20096            // 157 * 128
#define MCOLS  1024
#define NEDGE  640000
#define DD     256

// ---------------- scratch (__device__ globals; zero-initialized bss) ----------------
__device__ float g_colemb[MCOLS * DD];
__device__ float g_h[NPAD * DD];
__device__ float g_h0[NPAD * 768];          // batched layer-0 output (3 branches)
__device__ float g_br0[NPAD * DD];
__device__ float g_br1[NPAD * DD];
__device__ float g_br2[NPAD * DD];
__device__ float g_deg[3 * NNODES];
__device__ float g_dinv[3 * NNODES];
__device__ int   g_hist[3 * NNODES];
__device__ int   g_cur[3 * NNODES];
__device__ int   g_start[3 * (NNODES + 1)];
__device__ int   g_src[3 * NEDGE];
__device__ float g_nrm[3 * NEDGE];
__device__ unsigned short g_nzidx[NNODES * 128];
__device__ int   g_nzcnt[NNODES];
// packed bf16 hi/lo planes (A operands), k-contiguous rows of 256
__device__ __nv_bfloat16 g_x0h[NPAD * DD];
__device__ __nv_bfloat16 g_x0l[NPAD * DD];
__device__ __nv_bfloat16 g_xh[NPAD * DD];
__device__ __nv_bfloat16 g_xl[NPAD * DD];
// transposed bf16 hi/lo weights, l-major: index w' = l*3+b, each [n=256][k=256]
__device__ __nv_bfloat16 g_Wh[9 * DD * DD];
__device__ __nv_bfloat16 g_Wl[9 * DD * DD];

// ---------------- projection: col_emb ----------------
__global__ void colemb_kernel(const float* __restrict__ pW1, const float* __restrict__ pb1,
                              const float* __restrict__ pW2, const float* __restrict__ pb2,
                              float* __restrict__ colemb) {
    int j = blockIdx.x;
    int d = threadIdx.x;
    float jf = (float)j;
    float acc = pb2[d];
#pragma unroll
    for (int k = 0; k < 16; k++) {
        float hk = fmaxf(jf * pW1[k] + pb1[k], 0.f);
        acc += hk * pW2[k * DD + d];
    }
    colemb[j * DD + d] = acc;
}

// ---------------- weight convert, all 9 in one launch; dst index w' = l*3+b ----------------
__global__ void wconv_kernel(const float* __restrict__ W0, const float* __restrict__ W1,
                             const float* __restrict__ W2,
                             __nv_bfloat16* __restrict__ Ht, __nv_bfloat16* __restrict__ Lt) {
    __shared__ float tile[32][33];
    int z = blockIdx.z;           // b*3 + l
    int b = z / 3, l = z % 3;
    const float* W = (b == 0) ? W0 : (b == 1) ? W1 : W2;
    W += (size_t)l * DD * DD;
    size_t dbase = (size_t)(l * 3 + b) * DD * DD;
    int n0 = blockIdx.x * 32, k0 = blockIdx.y * 32;
    int tx = threadIdx.x, ty = threadIdx.y;  // 32 x 8
#pragma unroll
    for (int i = 0; i < 32; i += 8)
        tile[ty + i][tx] = W[(size_t)(k0 + ty + i) * DD + n0 + tx];
    __syncthreads();
#pragma unroll
    for (int i = 0; i < 32; i += 8) {
        float v = tile[tx][ty + i];                 // W[k0+tx][n0+ty+i]
        __nv_bfloat16 h = __float2bfloat16(v);
        size_t o = dbase + (size_t)(n0 + ty + i) * DD + k0 + tx;
        Ht[o] = h;
        Lt[o] = __float2bfloat16(v - __bfloat162float(h));
    }
}

// ---------------- nzbuild: per-row nonzero column lists ----------------
__global__ void nzbuild_kernel(const float* __restrict__ init,
                               unsigned short* __restrict__ nzidx, int* __restrict__ nzcnt) {
    int i = blockIdx.x;
    int t = threadIdx.x;  // 256
    __shared__ int cnt;
    if (t == 0) cnt = 0;
    __syncthreads();
    const float* row = init + (size_t)i * MCOLS;
    for (int c = t; c < MCOLS; c += 256) {
        if (row[c] != 0.f) {
            int p = atomicAdd(&cnt, 1);
            if (p < 128) nzidx[(size_t)i * 128 + p] = (unsigned short)c;
        }
    }
    __syncthreads();
    if (t == 0) nzcnt[i] = (cnt < 128) ? cnt : 128;
}

// ---------------- x0gather: masked mean via smem-cached colemb slab -> bf16 hi/lo ----------
#define XROWS 208
__global__ void __launch_bounds__(256) x0gather_kernel(
    const float* __restrict__ colemb,
    const unsigned short* __restrict__ nzidx, const int* __restrict__ nzcnt,
    __nv_bfloat16* __restrict__ xh, __nv_bfloat16* __restrict__ xl) {
    extern __shared__ float tile[];  // [1024][32] floats = 128KB
    int tx = threadIdx.x, ty = threadIdx.y;  // 32 x 8
    int tid = ty * 32 + tx;
    int d0 = blockIdx.x * 32;
    // load slab: colemb[c][d0+j] -> tile[c*32+j]
#pragma unroll 8
    for (int i = 0; i < 128; i++) {
        int w = tid + i * 256;
        tile[w] = colemb[(size_t)(w >> 5) * DD + d0 + (w & 31)];
    }
    __syncthreads();
    for (int it = 0; it < XROWS / 8; it++) {
        int r = blockIdx.y * XROWS + it * 8 + ty;
        if (r >= NNODES) break;
        int n = nzcnt[r];
        const unsigned short* lst = nzidx + (size_t)r * 128;
        float acc = 0.f;
        int k = 0;
        for (; k + 3 < n; k += 4) {
            int c0 = lst[k], c1 = lst[k + 1], c2 = lst[k + 2], c3 = lst[k + 3];
            acc += tile[c0 * 32 + tx];
            acc += tile[c1 * 32 + tx];
            acc += tile[c2 * 32 + tx];
            acc += tile[c3 * 32 + tx];
        }
        for (; k < n; k++) acc += tile[(int)lst[k] * 32 + tx];
        float v = (n > 0) ? acc / (float)n : 0.f;
        __nv_bfloat16 h = __float2bfloat16(v);
        size_t off = (size_t)r * DD + d0 + tx;
        xh[off] = h;
        xl[off] = __float2bfloat16(v - __bfloat162float(h));
    }
}

// ---------------- per-branch graph prep (grid.z = branch) ----------------
__global__ void branch_init(float* __restrict__ deg, int* __restrict__ hist) {
    int i = blockIdx.x * blockDim.x + threadIdx.x;
    int b = blockIdx.z;
    if (i < NNODES) { deg[b * NNODES + i] = 1.0f; hist[b * NNODES + i] = 0; }
}

__global__ void edge_count(const int* __restrict__ ei0, const int* __restrict__ ei1,
                           const int* __restrict__ ei2,
                           const float* __restrict__ ea0, const float* __restrict__ ea1,
                           const float* __restrict__ ea2,
                           float* __restrict__ deg, int* __restrict__ hist) {
    int e = blockIdx.x * blockDim.x + threadIdx.x;
    int b = blockIdx.z;
    const int* ei = (b == 0) ? ei0 : (b == 1) ? ei1 : ei2;
    const float* ea = (b == 0) ? ea0 : (b == 1) ? ea1 : ea2;
    if (e < NEDGE) {
        int c = ei[NEDGE + e];
        atomicAdd(&deg[b * NNODES + c], ea[e]);
        atomicAdd(&hist[b * NNODES + c], 1);
    }
}

__global__ void dinv_kernel(const float* __restrict__ deg, float* __restrict__ dinv) {
    int i = blockIdx.x * blockDim.x + threadIdx.x;
    int b = blockIdx.z;
    if (i < NNODES) dinv[b * NNODES + i] = rsqrtf(deg[b * NNODES + i]);
}

__global__ void scan_kernel(const int* __restrict__ hist_g, int* __restrict__ start_g,
                            int* __restrict__ cur_g) {
    __shared__ int sm[1024];
    __shared__ int carry_s;
    int b = blockIdx.x;
    const int* hist = hist_g + b * NNODES;
    int* start = start_g + b * (NNODES + 1);
    int* cur = cur_g + b * NNODES;
    int t = threadIdx.x;
    if (t == 0) carry_s = 0;
    __syncthreads();
    for (int c0 = 0; c0 < NNODES; c0 += 1024) {
        int idx = c0 + t;
        int v = (idx < NNODES) ? hist[idx] : 0;
        sm[t] = v;
        __syncthreads();
        for (int off = 1; off < 1024; off <<= 1) {
            int x = (t >= off) ? sm[t - off] : 0;
            __syncthreads();
            sm[t] += x;
            __syncthreads();
        }
        int incl = sm[t];
        int base = carry_s;
        __syncthreads();
        if (t == 1023) carry_s = base + incl;
        int excl = base + incl - v;
        if (idx < NNODES) { start[idx] = excl; cur[idx] = excl; }
        __syncthreads();
    }
    if (t == 0) start[NNODES] = carry_s;
}

__global__ void scatter_kernel(const int* __restrict__ ei0, const int* __restrict__ ei1,
                               const int* __restrict__ ei2,
                               const float* __restrict__ ea0, const float* __restrict__ ea1,
                               const float* __restrict__ ea2,
                               const float* __restrict__ dinv, int* __restrict__ cur,
                               int* __restrict__ src, float* __restrict__ nrm) {
    int e = blockIdx.x * blockDim.x + threadIdx.x;
    int b = blockIdx.z;
    const int* ei = (b == 0) ? ei0 : (b == 1) ? ei1 : ei2;
    const float* ea = (b == 0) ? ea0 : (b == 1) ? ea1 : ea2;
    if (e < NEDGE) {
        int r = ei[e];
        int c = ei[NEDGE + e];
        float n = dinv[b * NNODES + r] * ea[e] * dinv[b * NNODES + c];
        int p = atomicAdd(&cur[b * NNODES + c], 1);
        src[b * NEDGE + p] = r;
        nrm[b * NEDGE + p] = n;
    }
}

// ================= split-bf16 HMMA GEMM (preconverted operands, ldmatrix) =================
#define KC 64
#define PITCH 36      // uint32 words per smem row (32 kpairs + 4 pad)

__device__ __forceinline__ void mma_bf16(float* c, const uint32_t* a, const uint32_t* b) {
    asm volatile(
        "mma.sync.aligned.m16n8k16.row.col.f32.bf16.bf16.f32 "
        "{%0,%1,%2,%3}, {%4,%5,%6,%7}, {%8,%9}, {%0,%1,%2,%3};"
        : "+f"(c[0]), "+f"(c[1]), "+f"(c[2]), "+f"(c[3])
        : "r"(a[0]), "r"(a[1]), "r"(a[2]), "r"(a[3]), "r"(b[0]), "r"(b[1]));
}
__device__ __forceinline__ void ldsm4(uint32_t* r, uint32_t addr) {
    asm volatile("ldmatrix.sync.aligned.m8n8.x4.shared.b16 {%0,%1,%2,%3}, [%4];"
        : "=r"(r[0]), "=r"(r[1]), "=r"(r[2]), "=r"(r[3]) : "r"(addr));
}
__device__ __forceinline__ void cp16(uint32_t smem_dst, const void* gsrc) {
    asm volatile("cp.async.cg.shared.global [%0], [%1], 16;" :: "r"(smem_dst), "l"(gsrc));
}

__global__ void __launch_bounds__(256, 2) gemm_mma2(
    const __nv_bfloat16* __restrict__ Ah_g, const __nv_bfloat16* __restrict__ Al_g,
    const __nv_bfloat16* __restrict__ Bh_g, const __nv_bfloat16* __restrict__ Bl_g,
    float* __restrict__ C, int cstride) {
    extern __shared__ uint32_t smem[];
    uint32_t* sAh = smem;
    uint32_t* sAl = smem + 128 * PITCH;
    uint32_t* sBh = smem + 2 * 128 * PITCH;
    uint32_t* sBl = smem + 3 * 128 * PITCH;

    int tid = threadIdx.x;
    int lane = tid & 31, wid = tid >> 5;
    int g = lane >> 2, tig = lane & 3;
    int wm = wid & 1, wn = wid >> 1;
    int bm = blockIdx.x * 128;
    int bn = blockIdx.y * 128;

    uint32_t sAh_a = (uint32_t)__cvta_generic_to_shared(sAh);
    uint32_t sAl_a = (uint32_t)__cvta_generic_to_shared(sAl);
    uint32_t sBh_a = (uint32_t)__cvta_generic_to_shared(sBh);
    uint32_t sBl_a = (uint32_t)__cvta_generic_to_shared(sBl);

    int lane15 = lane & 15;
    int khalf = lane >> 4;  // 0/1
    uint32_t A_loff = (uint32_t)((wm * 64 + lane15) * PITCH) * 4u + (uint32_t)khalf * 16u;
    int bnrow = wn * 32 + (lane >> 4) * 8 + (lane & 7);
    uint32_t B_loff = (uint32_t)(bnrow * PITCH) * 4u + (uint32_t)((lane >> 3) & 1) * 16u;

    float acc[4][4][4];
#pragma unroll
    for (int mt = 0; mt < 4; mt++)
#pragma unroll
        for (int nt = 0; nt < 4; nt++)
#pragma unroll
            for (int q = 0; q < 4; q++) acc[mt][nt][q] = 0.f;

    for (int k0 = 0; k0 < DD; k0 += KC) {
#pragma unroll
        for (int i = 0; i < 4; i++) {
            int sl = tid + i * 256;
            int row = sl >> 3;
            int s = sl & 7;
            uint32_t so = (uint32_t)(row * PITCH + s * 4) * 4u;
            size_t ga = (size_t)(bm + row) * DD + k0 + s * 8;
            size_t gb = (size_t)(bn + row) * DD + k0 + s * 8;
            cp16(sAh_a + so, Ah_g + ga);
            cp16(sAl_a + so, Al_g + ga);
            cp16(sBh_a + so, Bh_g + gb);
            cp16(sBl_a + so, Bl_g + gb);
        }
        asm volatile("cp.async.commit_group;");
        asm volatile("cp.async.wait_group 0;");
        __syncthreads();

#pragma unroll
        for (int ks = 0; ks < 4; ks++) {
            uint32_t koff = (uint32_t)ks * 32u;
            uint32_t Bh[4][2], Bl[4][2];
#pragma unroll
            for (int ntp = 0; ntp < 2; ntp++) {
                uint32_t r[4];
                uint32_t off = B_loff + (uint32_t)(ntp * 16 * PITCH) * 4u + koff;
                ldsm4(r, sBh_a + off);
                Bh[2 * ntp][0] = r[0]; Bh[2 * ntp][1] = r[1];
                Bh[2 * ntp + 1][0] = r[2]; Bh[2 * ntp + 1][1] = r[3];
                ldsm4(r, sBl_a + off);
                Bl[2 * ntp][0] = r[0]; Bl[2 * ntp][1] = r[1];
                Bl[2 * ntp + 1][0] = r[2]; Bl[2 * ntp + 1][1] = r[3];
            }
#pragma unroll
            for (int mt = 0; mt < 4; mt++) {
                uint32_t off = A_loff + (uint32_t)(mt * 16 * PITCH) * 4u + koff;
                uint32_t Ah[4], Al[4];
                ldsm4(Ah, sAh_a + off);
                ldsm4(Al, sAl_a + off);
#pragma unroll
                for (int nt = 0; nt < 4; nt++) {
                    mma_bf16(acc[mt][nt], Ah, Bh[nt]);
                    mma_bf16(acc[mt][nt], Al, Bh[nt]);
                    mma_bf16(acc[mt][nt], Ah, Bl[nt]);
                }
            }
        }
        __syncthreads();
    }

#pragma unroll
    for (int mt = 0; mt < 4; mt++) {
        int row = bm + wm * 64 + mt * 16 + g;
#pragma unroll
        for (int nt = 0; nt < 4; nt++) {
            int col = bn + wn * 32 + nt * 8 + tig * 2;
            *(float2*)&C[(size_t)row * cstride + col] = make_float2(acc[mt][nt][0], acc[mt][nt][1]);
            *(float2*)&C[(size_t)(row + 8) * cstride + col] = make_float2(acc[mt][nt][2], acc[mt][nt][3]);
        }
    }
}

// ---------------- aggregation (+ optional relu'd bf16 hi/lo pack for next layer) --------
__global__ void __launch_bounds__(64) agg_kernel(const float* __restrict__ h, int hstride,
                           const int* __restrict__ src,
                           const float* __restrict__ nrm, const int* __restrict__ start,
                           const float* __restrict__ dinv, const float* __restrict__ bias,
                           float* __restrict__ out,
                           __nv_bfloat16* __restrict__ xh, __nv_bfloat16* __restrict__ xl,
                           int pack, int wf32) {
    int i = blockIdx.x;
    int t = threadIdx.x;  // 64, float4 each
    int s = start[i];
    int e = start[i + 1];
    float4 a0 = make_float4(0.f, 0.f, 0.f, 0.f);
    float4 a1 = make_float4(0.f, 0.f, 0.f, 0.f);
    float4 a2 = make_float4(0.f, 0.f, 0.f, 0.f);
    float4 a3 = make_float4(0.f, 0.f, 0.f, 0.f);
    int k = s;
    for (; k + 7 < e; k += 8) {
        int r0 = src[k], r1 = src[k + 1], r2 = src[k + 2], r3 = src[k + 3];
        int r4 = src[k + 4], r5 = src[k + 5], r6 = src[k + 6], r7 = src[k + 7];
        float w0 = nrm[k], w1 = nrm[k + 1], w2 = nrm[k + 2], w3 = nrm[k + 3];
        float w4 = nrm[k + 4], w5 = nrm[k + 5], w6 = nrm[k + 6], w7 = nrm[k + 7];
        float4 v0 = *(const float4*)&h[(size_t)r0 * hstride + t * 4];
        float4 v1 = *(const float4*)&h[(size_t)r1 * hstride + t * 4];
        float4 v2 = *(const float4*)&h[(size_t)r2 * hstride + t * 4];
        float4 v3 = *(const float4*)&h[(size_t)r3 * hstride + t * 4];
        float4 v4 = *(const float4*)&h[(size_t)r4 * hstride + t * 4];
        float4 v5 = *(const float4*)&h[(size_t)r5 * hstride + t * 4];
        float4 v6 = *(const float4*)&h[(size_t)r6 * hstride + t * 4];
        float4 v7 = *(const float4*)&h[(size_t)r7 * hstride + t * 4];
        a0.x += w0 * v0.x; a0.y += w0 * v0.y; a0.z += w0 * v0.z; a0.w += w0 * v0.w;
        a1.x += w1 * v1.x; a1.y += w1 * v1.y; a1.z += w1 * v1.z; a1.w += w1 * v1.w;
        a2.x += w2 * v2.x; a2.y += w2 * v2.y; a2.z += w2 * v2.z; a2.w += w2 * v2.w;
        a3.x += w3 * v3.x; a3.y += w3 * v3.y; a3.z += w3 * v3.z; a3.w += w3 * v3.w;
        a0.x += w4 * v4.x; a0.y += w4 * v4.y; a0.z += w4 * v4.z; a0.w += w4 * v4.w;
        a1.x += w5 * v5.x; a1.y += w5 * v5.y; a1.z += w5 * v5.z; a1.w += w5 * v5.w;
        a2.x += w6 * v6.x; a2.y += w6 * v6.y; a2.z += w6 * v6.z; a2.w += w6 * v6.w;
        a3.x += w7 * v7.x; a3.y += w7 * v7.y; a3.z += w7 * v7.z; a3.w += w7 * v7.w;
    }
    for (; k < e; k++) {
        int r = src[k];
        float w = nrm[k];
        float4 v = *(const float4*)&h[(size_t)r * hstride + t * 4];
        a0.x += w * v.x; a0.y += w * v.y; a0.z += w * v.z; a0.w += w * v.w;
    }
    float di = dinv[i];
    float sn = di * di;
    float4 hv = *(const float4*)&h[(size_t)i * hstride + t * 4];
    float4 bv = *(const float4*)&bias[t * 4];
    float4 acc;
    acc.x = a0.x + a1.x + a2.x + a3.x + sn * hv.x + bv.x;
    acc.y = a0.y + a1.y + a2.y + a3.y + sn * hv.y + bv.y;
    acc.z = a0.z + a1.z + a2.z + a3.z + sn * hv.z + bv.z;
    acc.w = a0.w + a1.w + a2.w + a3.w + sn * hv.w + bv.w;
    if (wf32) *(float4*)&out[(size_t)i * DD + t * 4] = acc;
    if (pack) {
        float r0 = fmaxf(acc.x, 0.f), r1 = fmaxf(acc.y, 0.f);
        float r2 = fmaxf(acc.z, 0.f), r3 = fmaxf(acc.w, 0.f);
        __nv_bfloat162 h01, h23, l01, l23;
        h01.x = __float2bfloat16(r0); h01.y = __float2bfloat16(r1);
        h23.x = __float2bfloat16(r2); h23.y = __float2bfloat16(r3);
        l01.x = __float2bfloat16(r0 - __bfloat162float(h01.x));
        l01.y = __float2bfloat16(r1 - __bfloat162float(h01.y));
        l23.x = __float2bfloat16(r2 - __bfloat162float(h23.x));
        l23.y = __float2bfloat16(r3 - __bfloat162float(h23.y));
        uint2 hp, lp;
        hp.x = *reinterpret_cast<uint32_t*>(&h01);
        hp.y = *reinterpret_cast<uint32_t*>(&h23);
        lp.x = *reinterpret_cast<uint32_t*>(&l01);
        lp.y = *reinterpret_cast<uint32_t*>(&l23);
        reinterpret_cast<uint2*>(xh)[(size_t)i * 64 + t] = hp;
        reinterpret_cast<uint2*>(xl)[(size_t)i * 64 + t] = lp;
    }
}

// ---------------- meta-path attention ----------------
__global__ void attn_kernel(const float* __restrict__ b0, const float* __restrict__ b1,
                            const float* __restrict__ b2, const float* __restrict__ watt,
                            float* __restrict__ out) {
    int i = blockIdx.x;
    int t = threadIdx.x;  // 256
    size_t off = (size_t)i * DD + t;
    float x0v = fmaxf(b0[off], 0.f);
    float x1v = fmaxf(b1[off], 0.f);
    float x2v = fmaxf(b2[off], 0.f);
    float w = watt[t];
    float s0 = x0v * w, s1 = x1v * w, s2 = x2v * w;
#pragma unroll
    for (int o = 16; o; o >>= 1) {
        s0 += __shfl_xor_sync(0xffffffffu, s0, o);
        s1 += __shfl_xor_sync(0xffffffffu, s1, o);
        s2 += __shfl_xor_sync(0xffffffffu, s2, o);
    }
    __shared__ float sm[3][8];
    __shared__ float sw[3];
    int wid = t >> 5, ln = t & 31;
    if (ln == 0) { sm[0][wid] = s0; sm[1][wid] = s1; sm[2][wid] = s2; }
    __syncthreads();
    if (t == 0) {
        float t0 = 0.f, t1 = 0.f, t2 = 0.f;
#pragma unroll
        for (int kk = 0; kk < 8; kk++) { t0 += sm[0][kk]; t1 += sm[1][kk]; t2 += sm[2][kk]; }
        float mx = fmaxf(t0, fmaxf(t1, t2));
        float e0 = expf(t0 - mx), e1 = expf(t1 - mx), e2 = expf(t2 - mx);
        float inv = 1.f / (e0 + e1 + e2);
        sw[0] = e0 * inv; sw[1] = e1 * inv; sw[2] = e2 * inv;
    }
    __syncthreads();
    out[off] = sw[0] * x0v + sw[1] * x1v + sw[2] * x2v;
}

// ---------------- launcher ----------------
extern "C" void kernel_launch(void* const* d_in, const int* in_sizes, int n_in,
                              void* d_out, int out_size) {
    const float* init = (const float*)d_in[0];
    const int*   ei[3] = {(const int*)d_in[1], (const int*)d_in[2], (const int*)d_in[3]};
    const float* ea[3] = {(const float*)d_in[4], (const float*)d_in[5], (const float*)d_in[6]};
    const float* pW1 = (const float*)d_in[7];
    const float* pb1 = (const float*)d_in[8];
    const float* pW2 = (const float*)d_in[9];
    const float* pb2 = (const float*)d_in[10];
    const float* Wb[3] = {(const float*)d_in[11], (const float*)d_in[13], (const float*)d_in[15]};
    const float* bb[3] = {(const float*)d_in[12], (const float*)d_in[14], (const float*)d_in[16]};
    const float* watt = (const float*)d_in[17];
    float* out = (float*)d_out;

    float *colemb, *h, *h0, *deg, *dinv, *nrm;
    float *br[3];
    int *hist, *cur, *start, *src, *nzcnt;
    unsigned short* nzidx;
    __nv_bfloat16 *x0h, *x0l, *xh, *xl, *Wh, *Wl;
    cudaGetSymbolAddress((void**)&colemb, g_colemb);
    cudaGetSymbolAddress((void**)&h,      g_h);
    cudaGetSymbolAddress((void**)&h0,     g_h0);
    cudaGetSymbolAddress((void**)&br[0],  g_br0);
    cudaGetSymbolAddress((void**)&br[1],  g_br1);
    cudaGetSymbolAddress((void**)&br[2],  g_br2);
    cudaGetSymbolAddress((void**)&deg,    g_deg);
    cudaGetSymbolAddress((void**)&dinv,   g_dinv);
    cudaGetSymbolAddress((void**)&hist,   g_hist);
    cudaGetSymbolAddress((void**)&cur,    g_cur);
    cudaGetSymbolAddress((void**)&start,  g_start);
    cudaGetSymbolAddress((void**)&src,    g_src);
    cudaGetSymbolAddress((void**)&nrm,    g_nrm);
    cudaGetSymbolAddress((void**)&nzidx,  g_nzidx);
    cudaGetSymbolAddress((void**)&nzcnt,  g_nzcnt);
    cudaGetSymbolAddress((void**)&x0h,    g_x0h);
    cudaGetSymbolAddress((void**)&x0l,    g_x0l);
    cudaGetSymbolAddress((void**)&xh,     g_xh);
    cudaGetSymbolAddress((void**)&xl,     g_xl);
    cudaGetSymbolAddress((void**)&Wh,     g_Wh);
    cudaGetSymbolAddress((void**)&Wl,     g_Wl);

    static int attr_set = 0;
    if (!attr_set) {
        cudaFuncSetAttribute(gemm_mma2, cudaFuncAttributeMaxDynamicSharedMemorySize,
                             4 * 128 * PITCH * 4);
        cudaFuncSetAttribute(x0gather_kernel, cudaFuncAttributeMaxDynamicSharedMemorySize,
                             MCOLS * 32 * 4);
        attr_set = 1;
    }

    const int NB = (NNODES + 255) / 256;
    const int EB = (NEDGE + 255) / 256;
    const int GSM = 4 * 128 * PITCH * 4;
    const int XSM = MCOLS * 32 * 4;
    const int XRB = (NNODES + XROWS - 1) / XROWS;

    // 1..4 (4th = x0gather, for ncu)
    colemb_kernel<<<MCOLS, DD>>>(pW1, pb1, pW2, pb2, colemb);
    wconv_kernel<<<dim3(8, 8, 9), dim3(32, 8)>>>(Wb[0], Wb[1], Wb[2], Wh, Wl);
    nzbuild_kernel<<<NNODES, 256>>>(init, nzidx, nzcnt);
    x0gather_kernel<<<dim3(8, XRB), dim3(32, 8), XSM>>>(colemb, nzidx, nzcnt, x0h, x0l);

    // graph prep, all branches
    branch_init<<<dim3(NB, 1, 3), 256>>>(deg, hist);
    edge_count<<<dim3(EB, 1, 3), 256>>>(ei[0], ei[1], ei[2], ea[0], ea[1], ea[2], deg, hist);
    dinv_kernel<<<dim3(NB, 1, 3), 256>>>(deg, dinv);
    scan_kernel<<<3, 1024>>>(hist, start, cur);
    scatter_kernel<<<dim3(EB, 1, 3), 256>>>(ei[0], ei[1], ei[2], ea[0], ea[1], ea[2],
                                            dinv, cur, src, nrm);

    // layer-0 GEMM batched across branches: Wh l-major => w'=0,1,2 contiguous [768][256]
    gemm_mma2<<<dim3(NPAD / 128, 6), 256, GSM>>>(x0h, x0l, Wh, Wl, h0, 768);

    for (int b = 0; b < 3; b++) {
        const int* sb = src + b * NEDGE;
        const float* nb = nrm + b * NEDGE;
        const int* stb = start + b * (NNODES + 1);
        const float* db = dinv + b * NNODES;

        agg_kernel<<<NNODES, 64>>>(h0 + b * DD, 768, sb, nb, stb, db, bb[b],
                                   br[b], xh, xl, 1, 0);
        for (int l = 1; l < 3; l++) {
            int w = l * 3 + b;
            gemm_mma2<<<dim3(NPAD / 128, 2), 256, GSM>>>(xh, xl,
                                                         Wh + (size_t)w * DD * DD,
                                                         Wl + (size_t)w * DD * DD, h, DD);
            int last = (l == 2);
            agg_kernel<<<NNODES, 64>>>(h, DD, sb, nb, stb, db, bb[b] + l * DD,
                                       br[b], xh, xl, !last, last);
        }
    }

    attn_kernel<<<NNODES, 256>>>(br[0], br[1], br[2], watt, out);
}

// round 7
// speedup vs baseline: 1.2121x; 1.2121x over previous
#include <cuda_runtime.h>
#include <cuda_bf16.h>
#include <cstdint>

#define NNODES 20000
#define NPAD   20096            // 157 * 128
#define MCOLS  1024
#define NEDGE  640000
#define DD     256

// ---------------- scratch (__device__ globals; zero-initialized bss) ----------------
__device__ float g_colemb[MCOLS * DD];
__device__ float g_h[NPAD * DD];
__device__ float g_h0[NPAD * 768];          // batched layer-0 output (3 branches)
__device__ float g_br0[NPAD * DD];
__device__ float g_br1[NPAD * DD];
__device__ float g_br2[NPAD * DD];
__device__ float g_deg[3 * NNODES];
__device__ float g_dinv[3 * NNODES];
__device__ int   g_hist[3 * NNODES];
__device__ int   g_cur[3 * NNODES];
__device__ int   g_start[3 * (NNODES + 1)];
__device__ int   g_src[3 * NEDGE];
__device__ float g_nrm[3 * NEDGE];
// x0-as-GEMM operands
__device__ __nv_bfloat16 g_mask[NPAD * MCOLS];     // bf16 0/1 mask (padded rows stay 0)
__device__ float g_rcnt[NPAD];                     // 1/max(cnt,1) (padded rows 0)
__device__ __nv_bfloat16 g_colTh[DD * MCOLS];      // colemb^T hi [d][m]
__device__ __nv_bfloat16 g_colTl[DD * MCOLS];      // colemb^T lo
// packed bf16 hi/lo planes (A operands), k-contiguous rows of 256
__device__ __nv_bfloat16 g_x0h[NPAD * DD];
__device__ __nv_bfloat16 g_x0l[NPAD * DD];
__device__ __nv_bfloat16 g_xh[NPAD * DD];
__device__ __nv_bfloat16 g_xl[NPAD * DD];
// transposed bf16 hi/lo weights, l-major: index w' = l*3+b, each [n=256][k=256]
__device__ __nv_bfloat16 g_Wh[9 * DD * DD];
__device__ __nv_bfloat16 g_Wl[9 * DD * DD];

// ---------------- projection: col_emb ----------------
__global__ void colemb_kernel(const float* __restrict__ pW1, const float* __restrict__ pb1,
                              const float* __restrict__ pW2, const float* __restrict__ pb2,
                              float* __restrict__ colemb) {
    int j = blockIdx.x;
    int d = threadIdx.x;
    float jf = (float)j;
    float acc = pb2[d];
#pragma unroll
    for (int k = 0; k < 16; k++) {
        float hk = fmaxf(jf * pW1[k] + pb1[k], 0.f);
        acc += hk * pW2[k * DD + d];
    }
    colemb[j * DD + d] = acc;
}

// ---------------- maskbuild: bf16 mask + rcnt ----------------
__global__ void maskbuild_kernel(const float* __restrict__ init,
                                 __nv_bfloat16* __restrict__ mask, float* __restrict__ rcnt) {
    int i = blockIdx.x;
    int t = threadIdx.x;  // 256, 4 cols each
    __shared__ int scnt;
    if (t == 0) scnt = 0;
    __syncthreads();
    float4 v = *(const float4*)&init[(size_t)i * MCOLS + t * 4];
    float m0 = (v.x != 0.f) ? 1.f : 0.f;
    float m1 = (v.y != 0.f) ? 1.f : 0.f;
    float m2 = (v.z != 0.f) ? 1.f : 0.f;
    float m3 = (v.w != 0.f) ? 1.f : 0.f;
    int c = (int)(m0 + m1 + m2 + m3);
#pragma unroll
    for (int o = 16; o; o >>= 1) c += __shfl_xor_sync(0xffffffffu, c, o);
    if ((t & 31) == 0) atomicAdd(&scnt, c);
    __nv_bfloat162 p01, p23;
    p01.x = __float2bfloat16(m0); p01.y = __float2bfloat16(m1);
    p23.x = __float2bfloat16(m2); p23.y = __float2bfloat16(m3);
    uint2 pk;
    pk.x = *reinterpret_cast<uint32_t*>(&p01);
    pk.y = *reinterpret_cast<uint32_t*>(&p23);
    *reinterpret_cast<uint2*>(&mask[(size_t)i * MCOLS + t * 4]) = pk;
    __syncthreads();
    if (t == 0) rcnt[i] = 1.f / (float)max(scnt, 1);
}

// ---------------- colembT: transpose + hi/lo split ----------------
__global__ void colembT_kernel(const float* __restrict__ colemb,
                               __nv_bfloat16* __restrict__ Th, __nv_bfloat16* __restrict__ Tl) {
    __shared__ float tile[32][33];
    int j0 = blockIdx.x * 32, d0 = blockIdx.y * 32;
    int tx = threadIdx.x, ty = threadIdx.y;  // 32 x 8
#pragma unroll
    for (int i = 0; i < 32; i += 8)
        tile[ty + i][tx] = colemb[(size_t)(j0 + ty + i) * DD + d0 + tx];
    __syncthreads();
#pragma unroll
    for (int i = 0; i < 32; i += 8) {
        float v = tile[tx][ty + i];                 // colemb[j0+tx][d0+ty+i]
        __nv_bfloat16 h = __float2bfloat16(v);
        size_t o = (size_t)(d0 + ty + i) * MCOLS + j0 + tx;
        Th[o] = h;
        Tl[o] = __float2bfloat16(v - __bfloat162float(h));
    }
}

// ---------------- weight convert, all 9 in one launch; dst index w' = l*3+b ----------------
__global__ void wconv_kernel(const float* __restrict__ W0, const float* __restrict__ W1,
                             const float* __restrict__ W2,
                             __nv_bfloat16* __restrict__ Ht, __nv_bfloat16* __restrict__ Lt) {
    __shared__ float tile[32][33];
    int z = blockIdx.z;           // b*3 + l
    int b = z / 3, l = z % 3;
    const float* W = (b == 0) ? W0 : (b == 1) ? W1 : W2;
    W += (size_t)l * DD * DD;
    size_t dbase = (size_t)(l * 3 + b) * DD * DD;
    int n0 = blockIdx.x * 32, k0 = blockIdx.y * 32;
    int tx = threadIdx.x, ty = threadIdx.y;  // 32 x 8
#pragma unroll
    for (int i = 0; i < 32; i += 8)
        tile[ty + i][tx] = W[(size_t)(k0 + ty + i) * DD + n0 + tx];
    __syncthreads();
#pragma unroll
    for (int i = 0; i < 32; i += 8) {
        float v = tile[tx][ty + i];                 // W[k0+tx][n0+ty+i]
        __nv_bfloat16 h = __float2bfloat16(v);
        size_t o = dbase + (size_t)(n0 + ty + i) * DD + k0 + tx;
        Ht[o] = h;
        Lt[o] = __float2bfloat16(v - __bfloat162float(h));
    }
}

// ---------------- per-branch graph prep (grid.z = branch) ----------------
__global__ void branch_init(float* __restrict__ deg, int* __restrict__ hist) {
    int i = blockIdx.x * blockDim.x + threadIdx.x;
    int b = blockIdx.z;
    if (i < NNODES) { deg[b * NNODES + i] = 1.0f; hist[b * NNODES + i] = 0; }
}

__global__ void edge_count(const int* __restrict__ ei0, const int* __restrict__ ei1,
                           const int* __restrict__ ei2,
                           const float* __restrict__ ea0, const float* __restrict__ ea1,
                           const float* __restrict__ ea2,
                           float* __restrict__ deg, int* __restrict__ hist) {
    int e = blockIdx.x * blockDim.x + threadIdx.x;
    int b = blockIdx.z;
    const int* ei = (b == 0) ? ei0 : (b == 1) ? ei1 : ei2;
    const float* ea = (b == 0) ? ea0 : (b == 1) ? ea1 : ea2;
    if (e < NEDGE) {
        int c = ei[NEDGE + e];
        atomicAdd(&deg[b * NNODES + c], ea[e]);
        atomicAdd(&hist[b * NNODES + c], 1);
    }
}

__global__ void dinv_kernel(const float* __restrict__ deg, float* __restrict__ dinv) {
    int i = blockIdx.x * blockDim.x + threadIdx.x;
    int b = blockIdx.z;
    if (i < NNODES) dinv[b * NNODES + i] = rsqrtf(deg[b * NNODES + i]);
}

__global__ void scan_kernel(const int* __restrict__ hist_g, int* __restrict__ start_g,
                            int* __restrict__ cur_g) {
    __shared__ int sm[1024];
    __shared__ int carry_s;
    int b = blockIdx.x;
    const int* hist = hist_g + b * NNODES;
    int* start = start_g + b * (NNODES + 1);
    int* cur = cur_g + b * NNODES;
    int t = threadIdx.x;
    if (t == 0) carry_s = 0;
    __syncthreads();
    for (int c0 = 0; c0 < NNODES; c0 += 1024) {
        int idx = c0 + t;
        int v = (idx < NNODES) ? hist[idx] : 0;
        sm[t] = v;
        __syncthreads();
        for (int off = 1; off < 1024; off <<= 1) {
            int x = (t >= off) ? sm[t - off] : 0;
            __syncthreads();
            sm[t] += x;
            __syncthreads();
        }
        int incl = sm[t];
        int base = carry_s;
        __syncthreads();
        if (t == 1023) carry_s = base + incl;
        int excl = base + incl - v;
        if (idx < NNODES) { start[idx] = excl; cur[idx] = excl; }
        __syncthreads();
    }
    if (t == 0) start[NNODES] = carry_s;
}

__global__ void scatter_kernel(const int* __restrict__ ei0, const int* __restrict__ ei1,
                               const int* __restrict__ ei2,
                               const float* __restrict__ ea0, const float* __restrict__ ea1,
                               const float* __restrict__ ea2,
                               const float* __restrict__ dinv, int* __restrict__ cur,
                               int* __restrict__ src, float* __restrict__ nrm) {
    int e = blockIdx.x * blockDim.x + threadIdx.x;
    int b = blockIdx.z;
    const int* ei = (b == 0) ? ei0 : (b == 1) ? ei1 : ei2;
    const float* ea = (b == 0) ? ea0 : (b == 1) ? ea1 : ea2;
    if (e < NEDGE) {
        int r = ei[e];
        int c = ei[NEDGE + e];
        float n = dinv[b * NNODES + r] * ea[e] * dinv[b * NNODES + c];
        int p = atomicAdd(&cur[b * NNODES + c], 1);
        src[b * NEDGE + p] = r;
        nrm[b * NEDGE + p] = n;
    }
}

// ================= shared MMA helpers =================
#define KC 64
#define PITCH 36      // uint32 words per smem row (32 kpairs + 4 pad)

__device__ __forceinline__ void mma_bf16(float* c, const uint32_t* a, const uint32_t* b) {
    asm volatile(
        "mma.sync.aligned.m16n8k16.row.col.f32.bf16.bf16.f32 "
        "{%0,%1,%2,%3}, {%4,%5,%6,%7}, {%8,%9}, {%0,%1,%2,%3};"
        : "+f"(c[0]), "+f"(c[1]), "+f"(c[2]), "+f"(c[3])
        : "r"(a[0]), "r"(a[1]), "r"(a[2]), "r"(a[3]), "r"(b[0]), "r"(b[1]));
}
__device__ __forceinline__ void ldsm4(uint32_t* r, uint32_t addr) {
    asm volatile("ldmatrix.sync.aligned.m8n8.x4.shared.b16 {%0,%1,%2,%3}, [%4];"
        : "=r"(r[0]), "=r"(r[1]), "=r"(r[2]), "=r"(r[3]) : "r"(addr));
}
__device__ __forceinline__ void cp16(uint32_t smem_dst, const void* gsrc) {
    asm volatile("cp.async.cg.shared.global [%0], [%1], 16;" :: "r"(smem_dst), "l"(gsrc));
}
__device__ __forceinline__ uint32_t packsplit(float v0, float v1, uint32_t& lo) {
    __nv_bfloat162 h, l;
    h.x = __float2bfloat16(v0); h.y = __float2bfloat16(v1);
    l.x = __float2bfloat16(v0 - __bfloat162float(h.x));
    l.y = __float2bfloat16(v1 - __bfloat162float(h.y));
    lo = *reinterpret_cast<uint32_t*>(&l);
    return *reinterpret_cast<uint32_t*>(&h);
}

// ================= x0 GEMM: x0 = (mask @ colemb) * rcnt, packed to bf16 hi/lo ==========
// A = mask bf16 [NPAD][1024] (exact), B = colembT hi/lo [256][1024]. 2 MMA passes.
__global__ void __launch_bounds__(256, 2) x0gemm(
    const __nv_bfloat16* __restrict__ Am, const __nv_bfloat16* __restrict__ Bh_g,
    const __nv_bfloat16* __restrict__ Bl_g, const float* __restrict__ rcnt,
    __nv_bfloat16* __restrict__ xh, __nv_bfloat16* __restrict__ xl) {
    extern __shared__ uint32_t smem[];
    uint32_t* sA  = smem;
    uint32_t* sBh = smem + 128 * PITCH;
    uint32_t* sBl = smem + 2 * 128 * PITCH;

    int tid = threadIdx.x;
    int lane = tid & 31, wid = tid >> 5;
    int g = lane >> 2, tig = lane & 3;
    int wm = wid & 1, wn = wid >> 1;
    int bm = blockIdx.x * 128;
    int bn = blockIdx.y * 128;

    uint32_t sA_a  = (uint32_t)__cvta_generic_to_shared(sA);
    uint32_t sBh_a = (uint32_t)__cvta_generic_to_shared(sBh);
    uint32_t sBl_a = (uint32_t)__cvta_generic_to_shared(sBl);

    int lane15 = lane & 15;
    int khalf = lane >> 4;
    uint32_t A_loff = (uint32_t)((wm * 64 + lane15) * PITCH) * 4u + (uint32_t)khalf * 16u;
    int bnrow = wn * 32 + (lane >> 4) * 8 + (lane & 7);
    uint32_t B_loff = (uint32_t)(bnrow * PITCH) * 4u + (uint32_t)((lane >> 3) & 1) * 16u;

    float acc[4][4][4];
#pragma unroll
    for (int mt = 0; mt < 4; mt++)
#pragma unroll
        for (int nt = 0; nt < 4; nt++)
#pragma unroll
            for (int q = 0; q < 4; q++) acc[mt][nt][q] = 0.f;

    for (int k0 = 0; k0 < MCOLS; k0 += KC) {
#pragma unroll
        for (int i = 0; i < 4; i++) {
            int sl = tid + i * 256;
            int row = sl >> 3;
            int s = sl & 7;
            uint32_t so = (uint32_t)(row * PITCH + s * 4) * 4u;
            size_t ga = (size_t)(bm + row) * MCOLS + k0 + s * 8;
            size_t gb = (size_t)(bn + row) * MCOLS + k0 + s * 8;
            cp16(sA_a + so, Am + ga);
            cp16(sBh_a + so, Bh_g + gb);
            cp16(sBl_a + so, Bl_g + gb);
        }
        asm volatile("cp.async.commit_group;");
        asm volatile("cp.async.wait_group 0;");
        __syncthreads();

#pragma unroll
        for (int ks = 0; ks < 4; ks++) {
            uint32_t koff = (uint32_t)ks * 32u;
            uint32_t Bh[4][2], Bl[4][2];
#pragma unroll
            for (int ntp = 0; ntp < 2; ntp++) {
                uint32_t r[4];
                uint32_t off = B_loff + (uint32_t)(ntp * 16 * PITCH) * 4u + koff;
                ldsm4(r, sBh_a + off);
                Bh[2 * ntp][0] = r[0]; Bh[2 * ntp][1] = r[1];
                Bh[2 * ntp + 1][0] = r[2]; Bh[2 * ntp + 1][1] = r[3];
                ldsm4(r, sBl_a + off);
                Bl[2 * ntp][0] = r[0]; Bl[2 * ntp][1] = r[1];
                Bl[2 * ntp + 1][0] = r[2]; Bl[2 * ntp + 1][1] = r[3];
            }
#pragma unroll
            for (int mt = 0; mt < 4; mt++) {
                uint32_t off = A_loff + (uint32_t)(mt * 16 * PITCH) * 4u + koff;
                uint32_t Af[4];
                ldsm4(Af, sA_a + off);
#pragma unroll
                for (int nt = 0; nt < 4; nt++) {
                    mma_bf16(acc[mt][nt], Af, Bh[nt]);
                    mma_bf16(acc[mt][nt], Af, Bl[nt]);
                }
            }
        }
        __syncthreads();
    }

    // epilogue: scale by rcnt, split-pack to xh/xl
#pragma unroll
    for (int mt = 0; mt < 4; mt++) {
        int row = bm + wm * 64 + mt * 16 + g;
        float rc0 = rcnt[row];
        float rc1 = rcnt[row + 8];
#pragma unroll
        for (int nt = 0; nt < 4; nt++) {
            int col = bn + wn * 32 + nt * 8 + tig * 2;
            uint32_t lo;
            uint32_t hi = packsplit(acc[mt][nt][0] * rc0, acc[mt][nt][1] * rc0, lo);
            *reinterpret_cast<uint32_t*>(&xh[(size_t)row * DD + col]) = hi;
            *reinterpret_cast<uint32_t*>(&xl[(size_t)row * DD + col]) = lo;
            hi = packsplit(acc[mt][nt][2] * rc1, acc[mt][nt][3] * rc1, lo);
            *reinterpret_cast<uint32_t*>(&xh[(size_t)(row + 8) * DD + col]) = hi;
            *reinterpret_cast<uint32_t*>(&xl[(size_t)(row + 8) * DD + col]) = lo;
        }
    }
}

// ================= split-bf16 HMMA GEMM (preconverted operands, ldmatrix) =================
__global__ void __launch_bounds__(256, 2) gemm_mma2(
    const __nv_bfloat16* __restrict__ Ah_g, const __nv_bfloat16* __restrict__ Al_g,
    const __nv_bfloat16* __restrict__ Bh_g, const __nv_bfloat16* __restrict__ Bl_g,
    float* __restrict__ C, int cstride) {
    extern __shared__ uint32_t smem[];
    uint32_t* sAh = smem;
    uint32_t* sAl = smem + 128 * PITCH;
    uint32_t* sBh = smem + 2 * 128 * PITCH;
    uint32_t* sBl = smem + 3 * 128 * PITCH;

    int tid = threadIdx.x;
    int lane = tid & 31, wid = tid >> 5;
    int g = lane >> 2, tig = lane & 3;
    int wm = wid & 1, wn = wid >> 1;
    int bm = blockIdx.x * 128;
    int bn = blockIdx.y * 128;

    uint32_t sAh_a = (uint32_t)__cvta_generic_to_shared(sAh);
    uint32_t sAl_a = (uint32_t)__cvta_generic_to_shared(sAl);
    uint32_t sBh_a = (uint32_t)__cvta_generic_to_shared(sBh);
    uint32_t sBl_a = (uint32_t)__cvta_generic_to_shared(sBl);

    int lane15 = lane & 15;
    int khalf = lane >> 4;  // 0/1
    uint32_t A_loff = (uint32_t)((wm * 64 + lane15) * PITCH) * 4u + (uint32_t)khalf * 16u;
    int bnrow = wn * 32 + (lane >> 4) * 8 + (lane & 7);
    uint32_t B_loff = (uint32_t)(bnrow * PITCH) * 4u + (uint32_t)((lane >> 3) & 1) * 16u;

    float acc[4][4][4];
#pragma unroll
    for (int mt = 0; mt < 4; mt++)
#pragma unroll
        for (int nt = 0; nt < 4; nt++)
#pragma unroll
            for (int q = 0; q < 4; q++) acc[mt][nt][q] = 0.f;

    for (int k0 = 0; k0 < DD; k0 += KC) {
#pragma unroll
        for (int i = 0; i < 4; i++) {
            int sl = tid + i * 256;
            int row = sl >> 3;
            int s = sl & 7;
            uint32_t so = (uint32_t)(row * PITCH + s * 4) * 4u;
            size_t ga = (size_t)(bm + row) * DD + k0 + s * 8;
            size_t gb = (size_t)(bn + row) * DD + k0 + s * 8;
            cp16(sAh_a + so, Ah_g + ga);
            cp16(sAl_a + so, Al_g + ga);
            cp16(sBh_a + so, Bh_g + gb);
            cp16(sBl_a + so, Bl_g + gb);
        }
        asm volatile("cp.async.commit_group;");
        asm volatile("cp.async.wait_group 0;");
        __syncthreads();

#pragma unroll
        for (int ks = 0; ks < 4; ks++) {
            uint32_t koff = (uint32_t)ks * 32u;
            uint32_t Bh[4][2], Bl[4][2];
#pragma unroll
            for (int ntp = 0; ntp < 2; ntp++) {
                uint32_t r[4];
                uint32_t off = B_loff + (uint32_t)(ntp * 16 * PITCH) * 4u + koff;
                ldsm4(r, sBh_a + off);
                Bh[2 * ntp][0] = r[0]; Bh[2 * ntp][1] = r[1];
                Bh[2 * ntp + 1][0] = r[2]; Bh[2 * ntp + 1][1] = r[3];
                ldsm4(r, sBl_a + off);
                Bl[2 * ntp][0] = r[0]; Bl[2 * ntp][1] = r[1];
                Bl[2 * ntp + 1][0] = r[2]; Bl[2 * ntp + 1][1] = r[3];
            }
#pragma unroll
            for (int mt = 0; mt < 4; mt++) {
                uint32_t off = A_loff + (uint32_t)(mt * 16 * PITCH) * 4u + koff;
                uint32_t Ah[4], Al[4];
                ldsm4(Ah, sAh_a + off);
                ldsm4(Al, sAl_a + off);
#pragma unroll
                for (int nt = 0; nt < 4; nt++) {
                    mma_bf16(acc[mt][nt], Ah, Bh[nt]);
                    mma_bf16(acc[mt][nt], Al, Bh[nt]);
                    mma_bf16(acc[mt][nt], Ah, Bl[nt]);
                }
            }
        }
        __syncthreads();
    }

#pragma unroll
    for (int mt = 0; mt < 4; mt++) {
        int row = bm + wm * 64 + mt * 16 + g;
#pragma unroll
        for (int nt = 0; nt < 4; nt++) {
            int col = bn + wn * 32 + nt * 8 + tig * 2;
            *(float2*)&C[(size_t)row * cstride + col] = make_float2(acc[mt][nt][0], acc[mt][nt][1]);
            *(float2*)&C[(size_t)(row + 8) * cstride + col] = make_float2(acc[mt][nt][2], acc[mt][nt][3]);
        }
    }
}

// ---------------- aggregation (+ optional relu'd bf16 hi/lo pack for next layer) --------
__global__ void __launch_bounds__(64) agg_kernel(const float* __restrict__ h, int hstride,
                           const int* __restrict__ src,
                           const float* __restrict__ nrm, const int* __restrict__ start,
                           const float* __restrict__ dinv, const float* __restrict__ bias,
                           float* __restrict__ out,
                           __nv_bfloat16* __restrict__ xh, __nv_bfloat16* __restrict__ xl,
                           int pack, int wf32) {
    int i = blockIdx.x;
    int t = threadIdx.x;  // 64, float4 each
    int s = start[i];
    int e = start[i + 1];
    float4 a0 = make_float4(0.f, 0.f, 0.f, 0.f);
    float4 a1 = make_float4(0.f, 0.f, 0.f, 0.f);
    float4 a2 = make_float4(0.f, 0.f, 0.f, 0.f);
    float4 a3 = make_float4(0.f, 0.f, 0.f, 0.f);
    int k = s;
    for (; k + 7 < e; k += 8) {
        int r0 = src[k], r1 = src[k + 1], r2 = src[k + 2], r3 = src[k + 3];
        int r4 = src[k + 4], r5 = src[k + 5], r6 = src[k + 6], r7 = src[k + 7];
        float w0 = nrm[k], w1 = nrm[k + 1], w2 = nrm[k + 2], w3 = nrm[k + 3];
        float w4 = nrm[k + 4], w5 = nrm[k + 5], w6 = nrm[k + 6], w7 = nrm[k + 7];
        float4 v0 = *(const float4*)&h[(size_t)r0 * hstride + t * 4];
        float4 v1 = *(const float4*)&h[(size_t)r1 * hstride + t * 4];
        float4 v2 = *(const float4*)&h[(size_t)r2 * hstride + t * 4];
        float4 v3 = *(const float4*)&h[(size_t)r3 * hstride + t * 4];
        float4 v4 = *(const float4*)&h[(size_t)r4 * hstride + t * 4];
        float4 v5 = *(const float4*)&h[(size_t)r5 * hstride + t * 4];
        float4 v6 = *(const float4*)&h[(size_t)r6 * hstride + t * 4];
        float4 v7 = *(const float4*)&h[(size_t)r7 * hstride + t * 4];
        a0.x += w0 * v0.x; a0.y += w0 * v0.y; a0.z += w0 * v0.z; a0.w += w0 * v0.w;
        a1.x += w1 * v1.x; a1.y += w1 * v1.y; a1.z += w1 * v1.z; a1.w += w1 * v1.w;
        a2.x += w2 * v2.x; a2.y += w2 * v2.y; a2.z += w2 * v2.z; a2.w += w2 * v2.w;
        a3.x += w3 * v3.x; a3.y += w3 * v3.y; a3.z += w3 * v3.z; a3.w += w3 * v3.w;
        a0.x += w4 * v4.x; a0.y += w4 * v4.y; a0.z += w4 * v4.z; a0.w += w4 * v4.w;
        a1.x += w5 * v5.x; a1.y += w5 * v5.y; a1.z += w5 * v5.z; a1.w += w5 * v5.w;
        a2.x += w6 * v6.x; a2.y += w6 * v6.y; a2.z += w6 * v6.z; a2.w += w6 * v6.w;
        a3.x += w7 * v7.x; a3.y += w7 * v7.y; a3.z += w7 * v7.z; a3.w += w7 * v7.w;
    }
    for (; k < e; k++) {
        int r = src[k];
        float w = nrm[k];
        float4 v = *(const float4*)&h[(size_t)r * hstride + t * 4];
        a0.x += w * v.x; a0.y += w * v.y; a0.z += w * v.z; a0.w += w * v.w;
    }
    float di = dinv[i];
    float sn = di * di;
    float4 hv = *(const float4*)&h[(size_t)i * hstride + t * 4];
    float4 bv = *(const float4*)&bias[t * 4];
    float4 acc;
    acc.x = a0.x + a1.x + a2.x + a3.x + sn * hv.x + bv.x;
    acc.y = a0.y + a1.y + a2.y + a3.y + sn * hv.y + bv.y;
    acc.z = a0.z + a1.z + a2.z + a3.z + sn * hv.z + bv.z;
    acc.w = a0.w + a1.w + a2.w + a3.w + sn * hv.w + bv.w;
    if (wf32) *(float4*)&out[(size_t)i * DD + t * 4] = acc;
    if (pack) {
        float r0 = fmaxf(acc.x, 0.f), r1 = fmaxf(acc.y, 0.f);
        float r2 = fmaxf(acc.z, 0.f), r3 = fmaxf(acc.w, 0.f);
        uint32_t lo0, lo1;
        uint32_t hi0 = packsplit(r0, r1, lo0);
        uint32_t hi1 = packsplit(r2, r3, lo1);
        uint2 hp, lp;
        hp.x = hi0; hp.y = hi1;
        lp.x = lo0; lp.y = lo1;
        reinterpret_cast<uint2*>(xh)[(size_t)i * 64 + t] = hp;
        reinterpret_cast<uint2*>(xl)[(size_t)i * 64 + t] = lp;
    }
}

// ---------------- meta-path attention ----------------
__global__ void attn_kernel(const float* __restrict__ b0, const float* __restrict__ b1,
                            const float* __restrict__ b2, const float* __restrict__ watt,
                            float* __restrict__ out) {
    int i = blockIdx.x;
    int t = threadIdx.x;  // 256
    size_t off = (size_t)i * DD + t;
    float x0v = fmaxf(b0[off], 0.f);
    float x1v = fmaxf(b1[off], 0.f);
    float x2v = fmaxf(b2[off], 0.f);
    float w = watt[t];
    float s0 = x0v * w, s1 = x1v * w, s2 = x2v * w;
#pragma unroll
    for (int o = 16; o; o >>= 1) {
        s0 += __shfl_xor_sync(0xffffffffu, s0, o);
        s1 += __shfl_xor_sync(0xffffffffu, s1, o);
        s2 += __shfl_xor_sync(0xffffffffu, s2, o);
    }
    __shared__ float sm[3][8];
    __shared__ float sw[3];
    int wid = t >> 5, ln = t & 31;
    if (ln == 0) { sm[0][wid] = s0; sm[1][wid] = s1; sm[2][wid] = s2; }
    __syncthreads();
    if (t == 0) {
        float t0 = 0.f, t1 = 0.f, t2 = 0.f;
#pragma unroll
        for (int kk = 0; kk < 8; kk++) { t0 += sm[0][kk]; t1 += sm[1][kk]; t2 += sm[2][kk]; }
        float mx = fmaxf(t0, fmaxf(t1, t2));
        float e0 = expf(t0 - mx), e1 = expf(t1 - mx), e2 = expf(t2 - mx);
        float inv = 1.f / (e0 + e1 + e2);
        sw[0] = e0 * inv; sw[1] = e1 * inv; sw[2] = e2 * inv;
    }
    __syncthreads();
    out[off] = sw[0] * x0v + sw[1] * x1v + sw[2] * x2v;
}

// ---------------- launcher ----------------
extern "C" void kernel_launch(void* const* d_in, const int* in_sizes, int n_in,
                              void* d_out, int out_size) {
    const float* init = (const float*)d_in[0];
    const int*   ei[3] = {(const int*)d_in[1], (const int*)d_in[2], (const int*)d_in[3]};
    const float* ea[3] = {(const float*)d_in[4], (const float*)d_in[5], (const float*)d_in[6]};
    const float* pW1 = (const float*)d_in[7];
    const float* pb1 = (const float*)d_in[8];
    const float* pW2 = (const float*)d_in[9];
    const float* pb2 = (const float*)d_in[10];
    const float* Wb[3] = {(const float*)d_in[11], (const float*)d_in[13], (const float*)d_in[15]};
    const float* bb[3] = {(const float*)d_in[12], (const float*)d_in[14], (const float*)d_in[16]};
    const float* watt = (const float*)d_in[17];
    float* out = (float*)d_out;

    float *colemb, *h, *h0, *deg, *dinv, *nrm, *rcnt;
    float *br[3];
    int *hist, *cur, *start, *src;
    __nv_bfloat16 *x0h, *x0l, *xh, *xl, *Wh, *Wl, *mask, *colTh, *colTl;
    cudaGetSymbolAddress((void**)&colemb, g_colemb);
    cudaGetSymbolAddress((void**)&h,      g_h);
    cudaGetSymbolAddress((void**)&h0,     g_h0);
    cudaGetSymbolAddress((void**)&br[0],  g_br0);
    cudaGetSymbolAddress((void**)&br[1],  g_br1);
    cudaGetSymbolAddress((void**)&br[2],  g_br2);
    cudaGetSymbolAddress((void**)&deg,    g_deg);
    cudaGetSymbolAddress((void**)&dinv,   g_dinv);
    cudaGetSymbolAddress((void**)&hist,   g_hist);
    cudaGetSymbolAddress((void**)&cur,    g_cur);
    cudaGetSymbolAddress((void**)&start,  g_start);
    cudaGetSymbolAddress((void**)&src,    g_src);
    cudaGetSymbolAddress((void**)&nrm,    g_nrm);
    cudaGetSymbolAddress((void**)&rcnt,   g_rcnt);
    cudaGetSymbolAddress((void**)&mask,   g_mask);
    cudaGetSymbolAddress((void**)&colTh,  g_colTh);
    cudaGetSymbolAddress((void**)&colTl,  g_colTl);
    cudaGetSymbolAddress((void**)&x0h,    g_x0h);
    cudaGetSymbolAddress((void**)&x0l,    g_x0l);
    cudaGetSymbolAddress((void**)&xh,     g_xh);
    cudaGetSymbolAddress((void**)&xl,     g_xl);
    cudaGetSymbolAddress((void**)&Wh,     g_Wh);
    cudaGetSymbolAddress((void**)&Wl,     g_Wl);

    static int attr_set = 0;
    if (!attr_set) {
        cudaFuncSetAttribute(gemm_mma2, cudaFuncAttributeMaxDynamicSharedMemorySize,
                             4 * 128 * PITCH * 4);
        cudaFuncSetAttribute(x0gemm, cudaFuncAttributeMaxDynamicSharedMemorySize,
                             3 * 128 * PITCH * 4);
        attr_set = 1;
    }

    const int NB = (NNODES + 255) / 256;
    const int EB = (NEDGE + 255) / 256;
    const int GSM = 4 * 128 * PITCH * 4;
    const int XSM = 3 * 128 * PITCH * 4;

    // 1..4 (4th = x0gemm, for ncu)
    colemb_kernel<<<MCOLS, DD>>>(pW1, pb1, pW2, pb2, colemb);
    maskbuild_kernel<<<NNODES, 256>>>(init, mask, rcnt);
    colembT_kernel<<<dim3(32, 8), dim3(32, 8)>>>(colemb, colTh, colTl);
    x0gemm<<<dim3(NPAD / 128, 2), 256, XSM>>>(mask, colTh, colTl, rcnt, x0h, x0l);

    wconv_kernel<<<dim3(8, 8, 9), dim3(32, 8)>>>(Wb[0], Wb[1], Wb[2], Wh, Wl);

    // graph prep, all branches
    branch_init<<<dim3(NB, 1, 3), 256>>>(deg, hist);
    edge_count<<<dim3(EB, 1, 3), 256>>>(ei[0], ei[1], ei[2], ea[0], ea[1], ea[2], deg, hist);
    dinv_kernel<<<dim3(NB, 1, 3), 256>>>(deg, dinv);
    scan_kernel<<<3, 1024>>>(hist, start, cur);
    scatter_kernel<<<dim3(EB, 1, 3), 256>>>(ei[0], ei[1], ei[2], ea[0], ea[1], ea[2],
                                            dinv, cur, src, nrm);

    // layer-0 GEMM batched across branches: Wh l-major => w'=0,1,2 contiguous [768][256]
    gemm_mma2<<<dim3(NPAD / 128, 6), 256, GSM>>>(x0h, x0l, Wh, Wl, h0, 768);

    for (int b = 0; b < 3; b++) {
        const int* sb = src + b * NEDGE;
        const float* nb = nrm + b * NEDGE;
        const int* stb = start + b * (NNODES + 1);
        const float* db = dinv + b * NNODES;

        agg_kernel<<<NNODES, 64>>>(h0 + b * DD, 768, sb, nb, stb, db, bb[b],
                                   br[b], xh, xl, 1, 0);
        for (int l = 1; l < 3; l++) {
            int w = l * 3 + b;
            gemm_mma2<<<dim3(NPAD / 128, 2), 256, GSM>>>(xh, xl,
                                                         Wh + (size_t)w * DD * DD,
                                                         Wl + (size_t)w * DD * DD, h, DD);
            int last = (l == 2);
            agg_kernel<<<NNODES, 64>>>(h, DD, sb, nb, stb, db, bb[b] + l * DD,
                                       br[b], xh, xl, !last, last);
        }
    }

    attn_kernel<<<NNODES, 256>>>(br[0], br[1], br[2], watt, out);
}